// round 17
// baseline (speedup 1.0000x reference)
#include <cuda_runtime.h>
#include <cuda_bf16.h>
#include <cstdint>
#include <math.h>

// ---------------------------------------------------------------------------
// SchnetConv — R16 (persistent mma edge+node, bf16 hi/lo 3-term, fast ssp,
// register GEMM1->GEMM2 handoff) + WARP PHASE SKEW: the 4 warps sharing an
// SMSP start their block loops staggered by ~1/4 block so their MMA phases
// tile the tensor pipe instead of phase-locking.
// ---------------------------------------------------------------------------

#define Dc       64
#define Rc       128
#define N_MAX    100000
#define EDGE_GRID 296      // 2 CTAs/SM x 148 SMs
#define SKEW_CYC 5000

__device__ float g_s[(size_t)N_MAX * Dc];
__device__ float g_cnt[N_MAX];
// fragment-ordered weight image (uint4{hix,hiy,lox,loy} per (ks,nt,lane)):
// B1 [8ks][8nt][32] = 32KB | B2 [4ks][8nt][32] = 16KB | B3 = 16KB | B4 = 16KB
__device__ __align__(16) unsigned char g_Bimg[81920];

// edge SMEM layout (bytes)
#define OFF_B1    0
#define OFF_B2    32768
#define OFF_BIAS  49152     // b1[64], b2[64]
#define SMEM_EDGE 49664

// node SMEM layout (bytes)
#define NOFF_B3    0
#define NOFF_B4    16384
#define NOFF_BIAS  32768    // b3[64], b4[64]
#define SMEM_NODE  33280

// ---- helpers ---------------------------------------------------------------
__device__ __forceinline__ float ssp_f(float x) {
    float e = __expf(-fabsf(x));
    return fmaxf(x, 0.0f) + __logf(1.0f + e) - 0.69314718055994531f;
}
// x = hi + lo (bf16 each); packs (x0 -> low half, x1 -> high half)
__device__ __forceinline__ void split2(float x0, float x1, uint32_t& hi, uint32_t& lo) {
    asm("cvt.rn.bf16x2.f32 %0, %1, %2;" : "=r"(hi) : "f"(x1), "f"(x0));
    float h0 = __uint_as_float(hi << 16);
    float h1 = __uint_as_float(hi & 0xffff0000u);
    asm("cvt.rn.bf16x2.f32 %0, %1, %2;" : "=r"(lo) : "f"(x1 - h1), "f"(x0 - h0));
}
__device__ __forceinline__ void mma16816(float* c, const uint32_t* a, uint32_t b0, uint32_t b1) {
    asm volatile(
        "mma.sync.aligned.m16n8k16.row.col.f32.bf16.bf16.f32 "
        "{%0,%1,%2,%3}, {%4,%5,%6,%7}, {%8,%9}, {%0,%1,%2,%3};"
        : "+f"(c[0]), "+f"(c[1]), "+f"(c[2]), "+f"(c[3])
        : "r"(a[0]), "r"(a[1]), "r"(a[2]), "r"(a[3]), "r"(b0), "r"(b1));
}
// stagger the 4 warps that share an SMSP: (wid>>2) in {0,1} + co-CTA bit
__device__ __forceinline__ void phase_skew(int wid) {
    int units = (wid >> 2) + ((blockIdx.x >= 148) ? 2 : 0);
    long long dl = (long long)units * SKEW_CYC;
    if (dl > 0) {
        long long t0 = clock64();
        while (clock64() - t0 < dl) { }
    }
}

// ---------------------------------------------------------------------------
__global__ void zero_kernel(int n_nodes) {
    int i = blockIdx.x * 256 + threadIdx.x;
    int t4 = n_nodes * (Dc / 4);
    if (i < t4) ((float4*)g_s)[i] = make_float4(0.f, 0.f, 0.f, 0.f);
    if (i < n_nodes) g_cnt[i] = 0.0f;
}

// Build fragment-ordered hi/lo weight images for W1/W2/W3/W4.
__global__ void prep_kernel(const float* __restrict__ W1, const float* __restrict__ W2,
                            const float* __restrict__ W3, const float* __restrict__ W4) {
    int i = blockIdx.x * 256 + threadIdx.x;
    if (i < 2048) {   // B1: idx = (ks*8+nt)*32+lane
        int lane = i & 31, nt = (i >> 5) & 7, ks = i >> 8;
        int tid4 = lane & 3, g = lane >> 2;
        int k0 = ks * 16 + tid4 * 2;
        int n  = nt * 8 + g;
        float e00 = W1[(k0    ) * Dc + n], e01 = W1[(k0 + 1) * Dc + n];
        float e10 = W1[(k0 + 8) * Dc + n], e11 = W1[(k0 + 9) * Dc + n];
        uint32_t hx, lx, hy, ly;
        split2(e00, e01, hx, lx);
        split2(e10, e11, hy, ly);
        uint4 v; v.x = hx; v.y = hy; v.z = lx; v.w = ly;
        ((uint4*)g_Bimg)[i] = v;
    }
    if (i < 1024) {   // B2 / B3 / B4 (all 64x64)
        int lane = i & 31, nt = (i >> 5) & 7, ks = i >> 8;
        int tid4 = lane & 3, g = lane >> 2;
        int k0 = ks * 16 + tid4 * 2;
        int n  = nt * 8 + g;
        const float* Ws[3] = {W2, W3, W4};
        unsigned char* dsts[3] = {g_Bimg + 32768, g_Bimg + 49152, g_Bimg + 65536};
#pragma unroll
        for (int m = 0; m < 3; ++m) {
            const float* W = Ws[m];
            float e00 = W[(k0    ) * Dc + n], e01 = W[(k0 + 1) * Dc + n];
            float e10 = W[(k0 + 8) * Dc + n], e11 = W[(k0 + 9) * Dc + n];
            uint32_t hx, lx, hy, ly;
            split2(e00, e01, hx, lx);
            split2(e10, e11, hy, ly);
            uint4 v; v.x = hx; v.y = hy; v.z = lx; v.w = ly;
            ((uint4*)dsts[m])[i] = v;
        }
    }
}

// ---------------------------------------------------------------------------
// Persistent edge kernel: weights staged once, each warp grid-strides over
// 16-edge blocks; register GEMM1->GEMM2 handoff; SMSP phase skew at start.
// ---------------------------------------------------------------------------
__global__ __launch_bounds__(256, 2)
void edge_kernel(const float* __restrict__ bf, const float* __restrict__ eh,
                 const float* __restrict__ nh, const int* __restrict__ src,
                 const int* __restrict__ dst,
                 const float* __restrict__ b1, const float* __restrict__ b2,
                 int E, int nblk)
{
    extern __shared__ unsigned char smx[];
    const int t = threadIdx.x, w = t >> 5, lane = t & 31;
    const int g = lane >> 2, tid4 = lane & 3;

    // one-time stage: weight fragments (48KB) + biases
    {
        const uint4* gi = (const uint4*)g_Bimg;
        uint4* s = (uint4*)smx;
        for (int i = t; i < 3072; i += 256) s[i] = gi[i];
        float* sbias = (float*)(smx + OFF_BIAS);
        if (t < Dc) sbias[t] = b1[t];
        else if (t < 2 * Dc) sbias[t] = b2[t - Dc];
    }
    __syncthreads();
    phase_skew(w);

    const float* sb1 = (const float*)(smx + OFF_BIAS);
    const float* sb2 = sb1 + Dc;

    const int gw = blockIdx.x * 8 + w;       // global warp-stream id
    const int nstreams = gridDim.x * 8;

    for (int blk = gw; blk < nblk; blk += nstreams) {
        const int e0 = blk * 16;             // this warp's 16-edge block

        const int er0 = min(e0 + g,     E - 1);
        const int er1 = min(e0 + g + 8, E - 1);
        const bool v0 = (e0 + g)     < E;
        const bool v1 = (e0 + g + 8) < E;
        const float* p0 = bf + (size_t)er0 * Rc;
        const float* p1 = bf + (size_t)er1 * Rc;

        float acc[8][4];
#pragma unroll
        for (int nt = 0; nt < 8; ++nt)
#pragma unroll
            for (int q = 0; q < 4; ++q) acc[nt][q] = 0.f;

        // ---- GEMM1: f1raw = bf @ W1, K=128 (8 k-steps), N=64 (8 n-tiles) ----
#pragma unroll
        for (int ks = 0; ks < 8; ++ks) {
            const int k0 = ks * 16 + tid4 * 2;
            float2 x00 = *(const float2*)(p0 + k0);
            float2 x10 = *(const float2*)(p1 + k0);
            float2 x01 = *(const float2*)(p0 + k0 + 8);
            float2 x11 = *(const float2*)(p1 + k0 + 8);
            uint32_t aH[4], aL[4];
            split2(x00.x, x00.y, aH[0], aL[0]);
            split2(x10.x, x10.y, aH[1], aL[1]);
            split2(x01.x, x01.y, aH[2], aL[2]);
            split2(x11.x, x11.y, aH[3], aL[3]);
            const uint4* Bp = (const uint4*)(smx + OFF_B1) + (ks * 8) * 32 + lane;
#pragma unroll
            for (int nt = 0; nt < 8; ++nt) {
                uint4 bb = Bp[nt * 32];
                mma16816(acc[nt], aH, bb.x, bb.y);   // Ah*Bh
                mma16816(acc[nt], aH, bb.z, bb.w);   // Ah*Bl
                mma16816(acc[nt], aL, bb.x, bb.y);   // Al*Bh
            }
        }

        // ---- register handoff: bias + ssp + split -> GEMM2 A-fragments ----
        uint32_t a2H[4][4], a2L[4][4];
#pragma unroll
        for (int ks = 0; ks < 4; ++ks)
#pragma unroll
            for (int h = 0; h < 2; ++h) {
                int nt = 2 * ks + h;
                int n = nt * 8 + tid4 * 2;
                float f0 = ssp_f(acc[nt][0] + sb1[n]);
                float f1 = ssp_f(acc[nt][1] + sb1[n + 1]);
                float f2 = ssp_f(acc[nt][2] + sb1[n]);
                float f3 = ssp_f(acc[nt][3] + sb1[n + 1]);
                split2(f0, f1, a2H[ks][2 * h + 0], a2L[ks][2 * h + 0]);
                split2(f2, f3, a2H[ks][2 * h + 1], a2L[ks][2 * h + 1]);
            }
#pragma unroll
        for (int nt = 0; nt < 8; ++nt)
#pragma unroll
            for (int q = 0; q < 4; ++q) acc[nt][q] = 0.f;

        // ---- GEMM2: f2raw = f1 @ W2, K=64 (4 k-steps) ----
#pragma unroll
        for (int ks = 0; ks < 4; ++ks) {
            const uint4* Bp = (const uint4*)(smx + OFF_B2) + (ks * 8) * 32 + lane;
#pragma unroll
            for (int nt = 0; nt < 8; ++nt) {
                uint4 bb = Bp[nt * 32];
                mma16816(acc[nt], a2H[ks], bb.x, bb.y);
                mma16816(acc[nt], a2H[ks], bb.z, bb.w);
                mma16816(acc[nt], a2L[ks], bb.x, bb.y);
            }
        }

        // ---- epilogue: m = f2 * eh * nh[src]; red.global.v2 to g_s ----
        int sv0 = 0, dv0 = 0, sv1 = 0, dv1 = 0;
        if (v0) { sv0 = src[e0 + g];     dv0 = dst[e0 + g]; }
        if (v1) { sv1 = src[e0 + g + 8]; dv1 = dst[e0 + g + 8]; }
        if (tid4 == 0) {
            if (v0) atomicAdd(&g_cnt[dv0], 1.0f);
            if (v1) atomicAdd(&g_cnt[dv1], 1.0f);
        }
#pragma unroll
        for (int nt = 0; nt < 8; ++nt) {
            int n = nt * 8 + tid4 * 2;
            if (v0) {
                float f0 = ssp_f(acc[nt][0] + sb2[n]);
                float f1 = ssp_f(acc[nt][1] + sb2[n + 1]);
                float2 ev = *(const float2*)&eh[(size_t)(e0 + g) * Dc + n];
                float2 nv = *(const float2*)&nh[(size_t)sv0 * Dc + n];
                float m0 = f0 * ev.x * nv.x;
                float m1 = f1 * ev.y * nv.y;
                float* gp = &g_s[(size_t)dv0 * Dc + n];
                asm volatile("red.global.add.v2.f32 [%0], {%1, %2};"
                             :: "l"(gp), "f"(m0), "f"(m1) : "memory");
            }
            if (v1) {
                float f2 = ssp_f(acc[nt][2] + sb2[n]);
                float f3 = ssp_f(acc[nt][3] + sb2[n + 1]);
                float2 ev = *(const float2*)&eh[(size_t)(e0 + g + 8) * Dc + n];
                float2 nv = *(const float2*)&nh[(size_t)sv1 * Dc + n];
                float m2 = f2 * ev.x * nv.x;
                float m3 = f3 * ev.y * nv.y;
                float* gp = &g_s[(size_t)dv1 * Dc + n];
                asm volatile("red.global.add.v2.f32 [%0], {%1, %2};"
                             :: "l"(gp), "f"(m2), "f"(m3) : "memory");
            }
        }
    }
}

// ---------------------------------------------------------------------------
// Persistent mma node kernel: agg = g_s*inv_cnt -> MLP3 -> MLP4 -> out.
// Register handoff, per-warp streams, phase skew.
// ---------------------------------------------------------------------------
__global__ __launch_bounds__(256, 2)
void node_kernel(const float* __restrict__ b3, const float* __restrict__ b4,
                 float* __restrict__ out, int N, int nblk)
{
    extern __shared__ unsigned char smx[];
    const int t = threadIdx.x, w = t >> 5, lane = t & 31;
    const int g = lane >> 2, tid4 = lane & 3;

    // one-time stage: B3/B4 fragments (32KB) + biases
    {
        const uint4* gi = (const uint4*)(g_Bimg + 49152);
        uint4* s = (uint4*)smx;
        for (int i = t; i < 2048; i += 256) s[i] = gi[i];
        float* sbias = (float*)(smx + NOFF_BIAS);
        if (t < Dc) sbias[t] = b3[t];
        else if (t < 2 * Dc) sbias[t] = b4[t - Dc];
    }
    __syncthreads();
    phase_skew(w);

    const float* sb3 = (const float*)(smx + NOFF_BIAS);
    const float* sb4 = sb3 + Dc;

    const int gw = blockIdx.x * 8 + w;
    const int nstreams = gridDim.x * 8;

    for (int blk = gw; blk < nblk; blk += nstreams) {
        const int n0r = blk * 16;

        const int nr0 = min(n0r + g,     N - 1);
        const int nr1 = min(n0r + g + 8, N - 1);
        const bool v0 = (n0r + g)     < N;
        const bool v1 = (n0r + g + 8) < N;
        const float* p0 = g_s + (size_t)nr0 * Dc;
        const float* p1 = g_s + (size_t)nr1 * Dc;
        float c0 = g_cnt[nr0], c1 = g_cnt[nr1];
        const float inv0 = (c0 > 0.0f) ? (1.0f / c0) : 0.0f;
        const float inv1 = (c1 > 0.0f) ? (1.0f / c1) : 0.0f;

        float acc[8][4];
#pragma unroll
        for (int nt = 0; nt < 8; ++nt)
#pragma unroll
            for (int q = 0; q < 4; ++q) acc[nt][q] = 0.f;

        // ---- GEMM3: h1raw = agg @ W3, K=64 (4 k-steps) ----
#pragma unroll
        for (int ks = 0; ks < 4; ++ks) {
            const int k0 = ks * 16 + tid4 * 2;
            float2 x00 = *(const float2*)(p0 + k0);
            float2 x10 = *(const float2*)(p1 + k0);
            float2 x01 = *(const float2*)(p0 + k0 + 8);
            float2 x11 = *(const float2*)(p1 + k0 + 8);
            uint32_t aH[4], aL[4];
            split2(x00.x * inv0, x00.y * inv0, aH[0], aL[0]);
            split2(x10.x * inv1, x10.y * inv1, aH[1], aL[1]);
            split2(x01.x * inv0, x01.y * inv0, aH[2], aL[2]);
            split2(x11.x * inv1, x11.y * inv1, aH[3], aL[3]);
            const uint4* Bp = (const uint4*)(smx + NOFF_B3) + (ks * 8) * 32 + lane;
#pragma unroll
            for (int nt = 0; nt < 8; ++nt) {
                uint4 bb = Bp[nt * 32];
                mma16816(acc[nt], aH, bb.x, bb.y);
                mma16816(acc[nt], aH, bb.z, bb.w);
                mma16816(acc[nt], aL, bb.x, bb.y);
            }
        }

        // ---- register handoff: bias + ssp + split -> GEMM4 A-fragments ----
        uint32_t a2H[4][4], a2L[4][4];
#pragma unroll
        for (int ks = 0; ks < 4; ++ks)
#pragma unroll
            for (int h = 0; h < 2; ++h) {
                int nt = 2 * ks + h;
                int n = nt * 8 + tid4 * 2;
                float f0 = ssp_f(acc[nt][0] + sb3[n]);
                float f1 = ssp_f(acc[nt][1] + sb3[n + 1]);
                float f2 = ssp_f(acc[nt][2] + sb3[n]);
                float f3 = ssp_f(acc[nt][3] + sb3[n + 1]);
                split2(f0, f1, a2H[ks][2 * h + 0], a2L[ks][2 * h + 0]);
                split2(f2, f3, a2H[ks][2 * h + 1], a2L[ks][2 * h + 1]);
            }
#pragma unroll
        for (int nt = 0; nt < 8; ++nt)
#pragma unroll
            for (int q = 0; q < 4; ++q) acc[nt][q] = 0.f;

        // ---- GEMM4: outraw = h1 @ W4, K=64 (4 k-steps) ----
#pragma unroll
        for (int ks = 0; ks < 4; ++ks) {
            const uint4* Bp = (const uint4*)(smx + NOFF_B4) + (ks * 8) * 32 + lane;
#pragma unroll
            for (int nt = 0; nt < 8; ++nt) {
                uint4 bb = Bp[nt * 32];
                mma16816(acc[nt], a2H[ks], bb.x, bb.y);
                mma16816(acc[nt], a2H[ks], bb.z, bb.w);
                mma16816(acc[nt], a2L[ks], bb.x, bb.y);
            }
        }

        // ---- epilogue: out = ssp(acc + b4), float2 stores ----
#pragma unroll
        for (int nt = 0; nt < 8; ++nt) {
            int n = nt * 8 + tid4 * 2;
            if (v0) {
                float2 o;
                o.x = ssp_f(acc[nt][0] + sb4[n]);
                o.y = ssp_f(acc[nt][1] + sb4[n + 1]);
                *(float2*)&out[(size_t)(n0r + g) * Dc + n] = o;
            }
            if (v1) {
                float2 o;
                o.x = ssp_f(acc[nt][2] + sb4[n]);
                o.y = ssp_f(acc[nt][3] + sb4[n + 1]);
                *(float2*)&out[(size_t)(n0r + g + 8) * Dc + n] = o;
            }
        }
    }
}

// ---------------------------------------------------------------------------
extern "C" void kernel_launch(void* const* d_in, const int* in_sizes, int n_in,
                              void* d_out, int out_size)
{
    const float* bf  = (const float*)d_in[0];
    const float* eh  = (const float*)d_in[1];
    const float* nh  = (const float*)d_in[2];
    const int*   src = (const int*)  d_in[3];
    const int*   dst = (const int*)  d_in[4];
    const float* W1  = (const float*)d_in[5];
    const float* b1  = (const float*)d_in[6];
    const float* W2  = (const float*)d_in[7];
    const float* b2  = (const float*)d_in[8];
    const float* W3  = (const float*)d_in[9];
    const float* b3  = (const float*)d_in[10];
    const float* W4  = (const float*)d_in[11];
    const float* b4  = (const float*)d_in[12];

    int E = in_sizes[3];
    int N = in_sizes[2] / Dc;

    cudaFuncSetAttribute(edge_kernel, cudaFuncAttributeMaxDynamicSharedMemorySize, SMEM_EDGE);
    cudaFuncSetAttribute(node_kernel, cudaFuncAttributeMaxDynamicSharedMemorySize, SMEM_NODE);

    int zero_grid = (N * (Dc / 4) + 255) / 256;
    zero_kernel<<<zero_grid, 256>>>(N);

    prep_kernel<<<8, 256>>>(W1, W2, W3, W4);

    int nblk_e = (E + 15) / 16;
    edge_kernel<<<EDGE_GRID, 256, SMEM_EDGE>>>(bf, eh, nh, src, dst, b1, b2, E, nblk_e);

    int nblk_n = (N + 15) / 16;
    node_kernel<<<EDGE_GRID, 256, SMEM_NODE>>>(b3, b4, (float*)d_out, N, nblk_n);
}